// round 3
// baseline (speedup 1.0000x reference)
#include <cuda_runtime.h>

#define BATCH 4096
#define SEQT  256
#define DIN   32
#define HID   64
#define GATES 256
#define BT    32
#define NTHR  512
#define NCTA  128
#define WROW  512   // floats per k2 row of weights (256 n' * 2)
#define AROW  64    // floats per k2 row of activations (32 m * 2)

typedef unsigned long long u64;

// Permuted (n' = 4*cell + gate), k-pair-interleaved weights.
__device__ __align__(16) float g_W0p[32 * WROW];   // Whh0
__device__ __align__(16) float g_Wx0p[16 * WROW];  // Wih0 (read per step via uniform LDG)
__device__ __align__(16) float g_W1p[64 * WROW];   // [Wih1; Whh1]
__device__ __align__(16) float g_B0p[2 * GATES];   // {bias, 0} pairs, n' order
__device__ __align__(16) float g_B1p[2 * GATES];

__global__ void prep_kernel(const float* __restrict__ Wih0, const float* __restrict__ Whh0,
                            const float* __restrict__ bih0, const float* __restrict__ bhh0,
                            const float* __restrict__ Wih1, const float* __restrict__ Whh1,
                            const float* __restrict__ bih1, const float* __restrict__ bhh1)
{
    int i = blockIdx.x * blockDim.x + threadIdx.x;
    int stride = gridDim.x * blockDim.x;
    for (int j = i; j < 32 * WROW; j += stride) {
        int k2 = j / WROW, rr = j % WROW, np = rr >> 1, p = rr & 1;
        int n = (np & 3) * HID + (np >> 2);          // n' = 4u+g -> n = g*64+u
        g_W0p[j] = Whh0[n * HID + 2 * k2 + p];
    }
    for (int j = i; j < 16 * WROW; j += stride) {
        int k2 = j / WROW, rr = j % WROW, np = rr >> 1, p = rr & 1;
        int n = (np & 3) * HID + (np >> 2);
        g_Wx0p[j] = Wih0[n * DIN + 2 * k2 + p];
    }
    for (int j = i; j < 64 * WROW; j += stride) {
        int k2 = j / WROW, rr = j % WROW, np = rr >> 1, p = rr & 1;
        int n = (np & 3) * HID + (np >> 2);
        int k = 2 * k2 + p;
        g_W1p[j] = (k < HID) ? Wih1[n * HID + k] : Whh1[n * HID + (k - HID)];
    }
    for (int np = i; np < GATES; np += stride) {
        int n = (np & 3) * HID + (np >> 2);
        g_B0p[2 * np] = bih0[n] + bhh0[n]; g_B0p[2 * np + 1] = 0.0f;
        g_B1p[2 * np] = bih1[n] + bhh1[n]; g_B1p[2 * np + 1] = 0.0f;
    }
}

// ---- packed f32x2 helpers ----
__device__ __forceinline__ u64 fma2(u64 a, u64 b, u64 c) {
    u64 d;
    asm("fma.rn.f32x2 %0, %1, %2, %3;" : "=l"(d) : "l"(a), "l"(b), "l"(c));
    return d;
}
__device__ __forceinline__ float2 unpack2(u64 v) {
    float2 f;
    asm("mov.b64 {%0, %1}, %2;" : "=f"(f.x), "=f"(f.y) : "l"(v));
    return f;
}

// ---- fast activations (MUFU EX2/RCP, proven 2.4e-7 end-to-end) ----
__device__ __forceinline__ float fast_ex2(float x) {
    float y; asm("ex2.approx.f32 %0, %1;" : "=f"(y) : "f"(x)); return y;
}
__device__ __forceinline__ float fast_rcp(float x) {
    float y; asm("rcp.approx.f32 %0, %1;" : "=f"(y) : "f"(x)); return y;
}
__device__ __forceinline__ float sigf(float x) {
    return fast_rcp(1.0f + fast_ex2(-1.4426950408889634f * x));
}
__device__ __forceinline__ float tanhf_fast(float x) {
    x = fminf(fmaxf(x, -15.0f), 15.0f);
    float e = fast_ex2(-2.8853900817779268f * x);  // exp(-2x)
    return (1.0f - e) * fast_rcp(1.0f + e);
}

// smem GEMM fragment: lanes share n'-block (weight loads broadcast), differ in m.
template <int K2>
__device__ __forceinline__ void gemm_smem(const float* __restrict__ aT,
                                          const float* __restrict__ W,
                                          int aOff, int wOff, u64 acc[2][8])
{
#pragma unroll 4
    for (int k2 = 0; k2 < K2; k2++) {
        ulonglong2 a = *(const ulonglong2*)(aT + k2 * AROW + aOff);
#pragma unroll
        for (int j2 = 0; j2 < 4; j2++) {
            ulonglong2 wv = *(const ulonglong2*)(W + k2 * WROW + wOff + j2 * 4);
            acc[0][2 * j2]     = fma2(a.x, wv.x, acc[0][2 * j2]);
            acc[0][2 * j2 + 1] = fma2(a.x, wv.y, acc[0][2 * j2 + 1]);
            acc[1][2 * j2]     = fma2(a.y, wv.x, acc[1][2 * j2]);
            acc[1][2 * j2 + 1] = fma2(a.y, wv.y, acc[1][2 * j2 + 1]);
        }
    }
}

// global-weight GEMM fragment (Wih0): uniform-address LDG broadcast per half-warp.
template <int K2>
__device__ __forceinline__ void gemm_gw(const float* __restrict__ aT,
                                        const float* __restrict__ W,
                                        int aOff, int wOff, u64 acc[2][8])
{
#pragma unroll 4
    for (int k2 = 0; k2 < K2; k2++) {
        ulonglong2 a = *(const ulonglong2*)(aT + k2 * AROW + aOff);
#pragma unroll
        for (int j2 = 0; j2 < 4; j2++) {
            ulonglong2 wv = __ldg((const ulonglong2*)(W + k2 * WROW + wOff + j2 * 4));
            acc[0][2 * j2]     = fma2(a.x, wv.x, acc[0][2 * j2]);
            acc[0][2 * j2 + 1] = fma2(a.x, wv.y, acc[0][2 * j2 + 1]);
            acc[1][2 * j2]     = fma2(a.y, wv.x, acc[1][2 * j2]);
            acc[1][2 * j2 + 1] = fma2(a.y, wv.y, acc[1][2 * j2 + 1]);
        }
    }
}

__device__ __forceinline__ void acc_init(const float* __restrict__ sB, int wOff, u64 acc[2][8])
{
#pragma unroll
    for (int j2 = 0; j2 < 4; j2++) {
        ulonglong2 b = *(const ulonglong2*)(sB + wOff + j2 * 4);
        acc[0][2 * j2] = b.x; acc[0][2 * j2 + 1] = b.y;
        acc[1][2 * j2] = b.x; acc[1][2 * j2 + 1] = b.y;
    }
}

// acc[m][j], j = 4*cl + gate (gates i,f,g,o). 2 rows x 2 cells per lane.
__device__ __forceinline__ void lstm_update(u64 acc[2][8], float c[2][2], float* __restrict__ dst)
{
    float h[2][2];
#pragma unroll
    for (int m = 0; m < 2; m++) {
#pragma unroll
        for (int cl = 0; cl < 2; cl++) {
            float2 pi = unpack2(acc[m][4 * cl + 0]);
            float2 pf = unpack2(acc[m][4 * cl + 1]);
            float2 pg = unpack2(acc[m][4 * cl + 2]);
            float2 po = unpack2(acc[m][4 * cl + 3]);
            float iv = sigf(pi.x + pi.y);
            float fv = sigf(pf.x + pf.y);
            float gv = tanhf_fast(pg.x + pg.y);
            float ov = sigf(po.x + po.y);
            float cc = fv * c[m][cl] + iv * gv;
            c[m][cl] = cc;
            h[m][cl] = ov * tanhf_fast(cc);
        }
    }
    // [k2=cell/2][m][cell&1]: {h(m0,c0), h(m0,c1), h(m0+1,c0), h(m0+1,c1)}
    *(float4*)dst = make_float4(h[0][0], h[0][1], h[1][0], h[1][1]);
}

// Shared layout (floats)
#define OFF_W0 0
#define OFF_W1 (OFF_W0 + 32 * WROW)    // 16384
#define OFF_B0 (OFF_W1 + 64 * WROW)    // 49152
#define OFF_B1 (OFF_B0 + 2 * GATES)    // 49664
#define OFF_H0 (OFF_B1 + 2 * GATES)    // 50176
#define OFF_H1 (OFF_H0 + 32 * AROW)    // 52224
#define OFF_X  (OFF_H1 + 32 * AROW)    // 54272
#define SMEMF  (OFF_X + 16 * AROW)     // 55296 floats = 221184 B

__global__ void __launch_bounds__(NTHR, 1)
lstm_fused(const float* __restrict__ x,
           const float* __restrict__ W1h, const float* __restrict__ b1h,
           const float* __restrict__ W2h, const float* __restrict__ b2h,
           float* __restrict__ out)
{
    extern __shared__ float sm[];
    float* sW0 = sm + OFF_W0;
    float* sW1 = sm + OFF_W1;
    float* sB0 = sm + OFF_B0;
    float* sB1 = sm + OFF_B1;
    float* h0T = sm + OFF_H0;
    float* h1T = sm + OFF_H1;
    float* xT  = sm + OFF_X;

    const int tid = threadIdx.x;
    const int b0  = blockIdx.x * BT;

    // stage weights + zero states
    for (int i = tid; i < 32 * WROW / 4; i += NTHR)
        ((float4*)sW0)[i] = ((const float4*)g_W0p)[i];
    for (int i = tid; i < 64 * WROW / 4; i += NTHR)
        ((float4*)sW1)[i] = ((const float4*)g_W1p)[i];
    if (tid < 128)      ((float4*)sB0)[tid]       = ((const float4*)g_B0p)[tid];
    else if (tid < 256) ((float4*)sB1)[tid - 128] = ((const float4*)g_B1p)[tid - 128];
    for (int i = tid; i < 64 * AROW; i += NTHR) h0T[i] = 0.0f;  // h0T + h1T contiguous

    // lane mapping: warp w covers n' block [16w, 16w+16); halves h of 8 n'; rows 2r,2r+1
    const int lane = tid & 31;
    const int w    = tid >> 5;
    const int r    = lane & 15;
    const int hh   = lane >> 4;
    const int aOff = r * 4;                   // act float offset: m0*2, m0=2r
    const int wOff = w * 32 + hh * 16;        // n'base*2
    const int cb   = w * 4 + hh * 2;          // cell base = n'base/4
    const int hOff = (cb >> 1) * AROW + aOff; // h store offset (float4)

    // x staging: thread -> (row xm, float2 chunk xd)
    const int xm = tid >> 4;
    const int xd = tid & 15;
    const float* xrow = x + (size_t)(b0 + xm) * SEQT * DIN + xd * 2;

    float2 xv = *(const float2*)(xrow);           // x(0)
    *(float2*)(xT + xd * AROW + xm * 2) = xv;
    xv = *(const float2*)(xrow + DIN);            // prefetch x(1)
    __syncthreads();

    float c0[2][2] = {{0.f, 0.f}, {0.f, 0.f}};
    float c1[2][2] = {{0.f, 0.f}, {0.f, 0.f}};
    u64 acc[2][8];

    // prologue: gemm0(t=0)
    acc_init(sB0, wOff, acc);
    gemm_gw<16>(xT, g_Wx0p, aOff, wOff, acc);
    gemm_smem<32>(h0T, sW0, aOff, wOff, acc);

    for (int t = 0; t < SEQT; t++) {
        __syncthreads();                          // B1: gemm0(t) readers done
        lstm_update(acc, c0, h0T + hOff);         // write h0(t)
        *(float2*)(xT + xd * AROW + xm * 2) = xv; // stage x(t+1)
        int tn = (t + 2 < SEQT) ? t + 2 : SEQT - 1;
        xv = *(const float2*)(xrow + (size_t)tn * DIN);
        __syncthreads();                          // B2: h0(t), x(t+1) visible
        acc_init(sB1, wOff, acc);
        gemm_smem<32>(h0T, sW1, aOff, wOff, acc);            // Wih1 * h0(t)
        gemm_smem<32>(h1T, sW1 + 32 * WROW, aOff, wOff, acc);// Whh1 * h1(t-1)
        __syncthreads();                          // B3: gemm1 readers done
        lstm_update(acc, c1, h1T + hOff);         // write h1(t)
        if (t + 1 < SEQT) {                       // overlap gemm0(t+1)
            acc_init(sB0, wOff, acc);
            gemm_gw<16>(xT, g_Wx0p, aOff, wOff, acc);
            gemm_smem<32>(h0T, sW0, aOff, wOff, acc);
        }
    }
    __syncthreads();

    // ---- head: out[m] = b2 + sum_n W2[n] * relu(b1[n] + sum_k h1(k,m) W1[n,k]) ----
    {
        int m = tid >> 4;      // 0..31
        int q = tid & 15;      // 0..15
        float pm = 0.0f;
#pragma unroll
        for (int jj = 0; jj < 4; jj++) {
            int n = q * 4 + jj;
            float s = b1h[n];
#pragma unroll 8
            for (int k = 0; k < HID; k++)
                s += h1T[(k >> 1) * AROW + m * 2 + (k & 1)] * W1h[n * HID + k];
            pm += fmaxf(s, 0.0f) * W2h[n];
        }
#pragma unroll
        for (int off = 8; off > 0; off >>= 1)
            pm += __shfl_down_sync(0xffffffffu, pm, off, 16);
        if (q == 0) out[b0 + m] = pm + b2h[0];
    }
}

extern "C" void kernel_launch(void* const* d_in, const int* in_sizes, int n_in,
                              void* d_out, int out_size)
{
    const float* x    = (const float*)d_in[0];
    const float* Wih0 = (const float*)d_in[1];
    const float* Whh0 = (const float*)d_in[2];
    const float* bih0 = (const float*)d_in[3];
    const float* bhh0 = (const float*)d_in[4];
    const float* Wih1 = (const float*)d_in[5];
    const float* Whh1 = (const float*)d_in[6];
    const float* bih1 = (const float*)d_in[7];
    const float* bhh1 = (const float*)d_in[8];
    const float* W1   = (const float*)d_in[9];
    const float* b1   = (const float*)d_in[10];
    const float* W2   = (const float*)d_in[11];
    const float* b2   = (const float*)d_in[12];

    prep_kernel<<<64, 256>>>(Wih0, Whh0, bih0, bhh0, Wih1, Whh1, bih1, bhh1);

    size_t smem_bytes = (size_t)SMEMF * sizeof(float);   // 221184 B
    cudaFuncSetAttribute(lstm_fused,
                         cudaFuncAttributeMaxDynamicSharedMemorySize, (int)smem_bytes);
    lstm_fused<<<NCTA, NTHR, smem_bytes>>>(x, W1, b1, W2, b2, (float*)d_out);
}

// round 4
// speedup vs baseline: 1.0001x; 1.0001x over previous
#include <cuda_runtime.h>

#define BATCH 4096
#define SEQT  256
#define DIN   32
#define HID   64
#define GATES 256
#define BT    32
#define NTHR  512
#define NCTA  128
#define WROW  512   // floats per k2 row of weights (256 n' * 2)
#define AROW  64    // floats per k2 row of activations (32 m * 2)

typedef unsigned long long u64;

// Permuted (n' = 4*cell + gate), k-pair-interleaved weights.
__device__ __align__(16) float g_W0p[32 * WROW];   // Whh0
__device__ __align__(16) float g_Wx0p[16 * WROW];  // Wih0 (read per step via uniform LDG)
__device__ __align__(16) float g_W1p[64 * WROW];   // [Wih1; Whh1]
__device__ __align__(16) float g_B0p[2 * GATES];   // {bias, 0} pairs, n' order
__device__ __align__(16) float g_B1p[2 * GATES];

__global__ void prep_kernel(const float* __restrict__ Wih0, const float* __restrict__ Whh0,
                            const float* __restrict__ bih0, const float* __restrict__ bhh0,
                            const float* __restrict__ Wih1, const float* __restrict__ Whh1,
                            const float* __restrict__ bih1, const float* __restrict__ bhh1)
{
    int i = blockIdx.x * blockDim.x + threadIdx.x;
    int stride = gridDim.x * blockDim.x;
    for (int j = i; j < 32 * WROW; j += stride) {
        int k2 = j / WROW, rr = j % WROW, np = rr >> 1, p = rr & 1;
        int n = (np & 3) * HID + (np >> 2);          // n' = 4u+g -> n = g*64+u
        g_W0p[j] = Whh0[n * HID + 2 * k2 + p];
    }
    for (int j = i; j < 16 * WROW; j += stride) {
        int k2 = j / WROW, rr = j % WROW, np = rr >> 1, p = rr & 1;
        int n = (np & 3) * HID + (np >> 2);
        g_Wx0p[j] = Wih0[n * DIN + 2 * k2 + p];
    }
    for (int j = i; j < 64 * WROW; j += stride) {
        int k2 = j / WROW, rr = j % WROW, np = rr >> 1, p = rr & 1;
        int n = (np & 3) * HID + (np >> 2);
        int k = 2 * k2 + p;
        g_W1p[j] = (k < HID) ? Wih1[n * HID + k] : Whh1[n * HID + (k - HID)];
    }
    for (int np = i; np < GATES; np += stride) {
        int n = (np & 3) * HID + (np >> 2);
        g_B0p[2 * np] = bih0[n] + bhh0[n]; g_B0p[2 * np + 1] = 0.0f;
        g_B1p[2 * np] = bih1[n] + bhh1[n]; g_B1p[2 * np + 1] = 0.0f;
    }
}

// ---- packed f32x2 helpers ----
__device__ __forceinline__ u64 fma2(u64 a, u64 b, u64 c) {
    u64 d;
    asm("fma.rn.f32x2 %0, %1, %2, %3;" : "=l"(d) : "l"(a), "l"(b), "l"(c));
    return d;
}
__device__ __forceinline__ float2 unpack2(u64 v) {
    float2 f;
    asm("mov.b64 {%0, %1}, %2;" : "=f"(f.x), "=f"(f.y) : "l"(v));
    return f;
}

// ---- fast activations (MUFU EX2/RCP, proven 2.4e-7 end-to-end) ----
__device__ __forceinline__ float fast_ex2(float x) {
    float y; asm("ex2.approx.f32 %0, %1;" : "=f"(y) : "f"(x)); return y;
}
__device__ __forceinline__ float fast_rcp(float x) {
    float y; asm("rcp.approx.f32 %0, %1;" : "=f"(y) : "f"(x)); return y;
}
__device__ __forceinline__ float sigf(float x) {
    return fast_rcp(1.0f + fast_ex2(-1.4426950408889634f * x));
}
__device__ __forceinline__ float tanhf_fast(float x) {
    x = fminf(fmaxf(x, -15.0f), 15.0f);
    float e = fast_ex2(-2.8853900817779268f * x);  // exp(-2x)
    return (1.0f - e) * fast_rcp(1.0f + e);
}

// smem GEMM fragment: lanes share n'-block (weight loads broadcast), differ in m.
template <int K2>
__device__ __forceinline__ void gemm_smem(const float* __restrict__ aT,
                                          const float* __restrict__ W,
                                          int aOff, int wOff, u64 acc[2][8])
{
#pragma unroll 4
    for (int k2 = 0; k2 < K2; k2++) {
        ulonglong2 a = *(const ulonglong2*)(aT + k2 * AROW + aOff);
#pragma unroll
        for (int j2 = 0; j2 < 4; j2++) {
            ulonglong2 wv = *(const ulonglong2*)(W + k2 * WROW + wOff + j2 * 4);
            acc[0][2 * j2]     = fma2(a.x, wv.x, acc[0][2 * j2]);
            acc[0][2 * j2 + 1] = fma2(a.x, wv.y, acc[0][2 * j2 + 1]);
            acc[1][2 * j2]     = fma2(a.y, wv.x, acc[1][2 * j2]);
            acc[1][2 * j2 + 1] = fma2(a.y, wv.y, acc[1][2 * j2 + 1]);
        }
    }
}

// global-weight GEMM fragment (Wih0): uniform-address LDG broadcast per half-warp.
template <int K2>
__device__ __forceinline__ void gemm_gw(const float* __restrict__ aT,
                                        const float* __restrict__ W,
                                        int aOff, int wOff, u64 acc[2][8])
{
#pragma unroll 4
    for (int k2 = 0; k2 < K2; k2++) {
        ulonglong2 a = *(const ulonglong2*)(aT + k2 * AROW + aOff);
#pragma unroll
        for (int j2 = 0; j2 < 4; j2++) {
            ulonglong2 wv = __ldg((const ulonglong2*)(W + k2 * WROW + wOff + j2 * 4));
            acc[0][2 * j2]     = fma2(a.x, wv.x, acc[0][2 * j2]);
            acc[0][2 * j2 + 1] = fma2(a.x, wv.y, acc[0][2 * j2 + 1]);
            acc[1][2 * j2]     = fma2(a.y, wv.x, acc[1][2 * j2]);
            acc[1][2 * j2 + 1] = fma2(a.y, wv.y, acc[1][2 * j2 + 1]);
        }
    }
}

__device__ __forceinline__ void acc_init(const float* __restrict__ sB, int wOff, u64 acc[2][8])
{
#pragma unroll
    for (int j2 = 0; j2 < 4; j2++) {
        ulonglong2 b = *(const ulonglong2*)(sB + wOff + j2 * 4);
        acc[0][2 * j2] = b.x; acc[0][2 * j2 + 1] = b.y;
        acc[1][2 * j2] = b.x; acc[1][2 * j2 + 1] = b.y;
    }
}

// acc[m][j], j = 4*cl + gate (gates i,f,g,o). 2 rows x 2 cells per lane.
__device__ __forceinline__ void lstm_update(u64 acc[2][8], float c[2][2], float* __restrict__ dst)
{
    float h[2][2];
#pragma unroll
    for (int m = 0; m < 2; m++) {
#pragma unroll
        for (int cl = 0; cl < 2; cl++) {
            float2 pi = unpack2(acc[m][4 * cl + 0]);
            float2 pf = unpack2(acc[m][4 * cl + 1]);
            float2 pg = unpack2(acc[m][4 * cl + 2]);
            float2 po = unpack2(acc[m][4 * cl + 3]);
            float iv = sigf(pi.x + pi.y);
            float fv = sigf(pf.x + pf.y);
            float gv = tanhf_fast(pg.x + pg.y);
            float ov = sigf(po.x + po.y);
            float cc = fv * c[m][cl] + iv * gv;
            c[m][cl] = cc;
            h[m][cl] = ov * tanhf_fast(cc);
        }
    }
    // [k2=cell/2][m][cell&1]: {h(m0,c0), h(m0,c1), h(m0+1,c0), h(m0+1,c1)}
    *(float4*)dst = make_float4(h[0][0], h[0][1], h[1][0], h[1][1]);
}

// Shared layout (floats)
#define OFF_W0 0
#define OFF_W1 (OFF_W0 + 32 * WROW)    // 16384
#define OFF_B0 (OFF_W1 + 64 * WROW)    // 49152
#define OFF_B1 (OFF_B0 + 2 * GATES)    // 49664
#define OFF_H0 (OFF_B1 + 2 * GATES)    // 50176
#define OFF_H1 (OFF_H0 + 32 * AROW)    // 52224
#define OFF_X  (OFF_H1 + 32 * AROW)    // 54272
#define SMEMF  (OFF_X + 16 * AROW)     // 55296 floats = 221184 B

__global__ void __launch_bounds__(NTHR, 1)
lstm_fused(const float* __restrict__ x,
           const float* __restrict__ W1h, const float* __restrict__ b1h,
           const float* __restrict__ W2h, const float* __restrict__ b2h,
           float* __restrict__ out)
{
    extern __shared__ float sm[];
    float* sW0 = sm + OFF_W0;
    float* sW1 = sm + OFF_W1;
    float* sB0 = sm + OFF_B0;
    float* sB1 = sm + OFF_B1;
    float* h0T = sm + OFF_H0;
    float* h1T = sm + OFF_H1;
    float* xT  = sm + OFF_X;

    const int tid = threadIdx.x;
    const int b0  = blockIdx.x * BT;

    // stage weights + zero states
    for (int i = tid; i < 32 * WROW / 4; i += NTHR)
        ((float4*)sW0)[i] = ((const float4*)g_W0p)[i];
    for (int i = tid; i < 64 * WROW / 4; i += NTHR)
        ((float4*)sW1)[i] = ((const float4*)g_W1p)[i];
    if (tid < 128)      ((float4*)sB0)[tid]       = ((const float4*)g_B0p)[tid];
    else if (tid < 256) ((float4*)sB1)[tid - 128] = ((const float4*)g_B1p)[tid - 128];
    for (int i = tid; i < 64 * AROW; i += NTHR) h0T[i] = 0.0f;  // h0T + h1T contiguous

    // lane mapping: warp w covers n' block [16w, 16w+16); halves h of 8 n'; rows 2r,2r+1
    const int lane = tid & 31;
    const int w    = tid >> 5;
    const int r    = lane & 15;
    const int hh   = lane >> 4;
    const int aOff = r * 4;                   // act float offset: m0*2, m0=2r
    const int wOff = w * 32 + hh * 16;        // n'base*2
    const int cb   = w * 4 + hh * 2;          // cell base = n'base/4
    const int hOff = (cb >> 1) * AROW + aOff; // h store offset (float4)

    // x staging: thread -> (row xm, float2 chunk xd)
    const int xm = tid >> 4;
    const int xd = tid & 15;
    const float* xrow = x + (size_t)(b0 + xm) * SEQT * DIN + xd * 2;

    float2 xv = *(const float2*)(xrow);           // x(0)
    *(float2*)(xT + xd * AROW + xm * 2) = xv;
    xv = *(const float2*)(xrow + DIN);            // prefetch x(1)
    __syncthreads();

    float c0[2][2] = {{0.f, 0.f}, {0.f, 0.f}};
    float c1[2][2] = {{0.f, 0.f}, {0.f, 0.f}};
    u64 acc[2][8];

    // prologue: gemm0(t=0)
    acc_init(sB0, wOff, acc);
    gemm_gw<16>(xT, g_Wx0p, aOff, wOff, acc);
    gemm_smem<32>(h0T, sW0, aOff, wOff, acc);

    for (int t = 0; t < SEQT; t++) {
        __syncthreads();                          // B1: gemm0(t) readers done
        lstm_update(acc, c0, h0T + hOff);         // write h0(t)
        *(float2*)(xT + xd * AROW + xm * 2) = xv; // stage x(t+1)
        int tn = (t + 2 < SEQT) ? t + 2 : SEQT - 1;
        xv = *(const float2*)(xrow + (size_t)tn * DIN);
        __syncthreads();                          // B2: h0(t), x(t+1) visible
        acc_init(sB1, wOff, acc);
        gemm_smem<32>(h0T, sW1, aOff, wOff, acc);            // Wih1 * h0(t)
        gemm_smem<32>(h1T, sW1 + 32 * WROW, aOff, wOff, acc);// Whh1 * h1(t-1)
        __syncthreads();                          // B3: gemm1 readers done
        lstm_update(acc, c1, h1T + hOff);         // write h1(t)
        if (t + 1 < SEQT) {                       // overlap gemm0(t+1)
            acc_init(sB0, wOff, acc);
            gemm_gw<16>(xT, g_Wx0p, aOff, wOff, acc);
            gemm_smem<32>(h0T, sW0, aOff, wOff, acc);
        }
    }
    __syncthreads();

    // ---- head: out[m] = b2 + sum_n W2[n] * relu(b1[n] + sum_k h1(k,m) W1[n,k]) ----
    {
        int m = tid >> 4;      // 0..31
        int q = tid & 15;      // 0..15
        float pm = 0.0f;
#pragma unroll
        for (int jj = 0; jj < 4; jj++) {
            int n = q * 4 + jj;
            float s = b1h[n];
#pragma unroll 8
            for (int k = 0; k < HID; k++)
                s += h1T[(k >> 1) * AROW + m * 2 + (k & 1)] * W1h[n * HID + k];
            pm += fmaxf(s, 0.0f) * W2h[n];
        }
#pragma unroll
        for (int off = 8; off > 0; off >>= 1)
            pm += __shfl_down_sync(0xffffffffu, pm, off, 16);
        if (q == 0) out[b0 + m] = pm + b2h[0];
    }
}

extern "C" void kernel_launch(void* const* d_in, const int* in_sizes, int n_in,
                              void* d_out, int out_size)
{
    const float* x    = (const float*)d_in[0];
    const float* Wih0 = (const float*)d_in[1];
    const float* Whh0 = (const float*)d_in[2];
    const float* bih0 = (const float*)d_in[3];
    const float* bhh0 = (const float*)d_in[4];
    const float* Wih1 = (const float*)d_in[5];
    const float* Whh1 = (const float*)d_in[6];
    const float* bih1 = (const float*)d_in[7];
    const float* bhh1 = (const float*)d_in[8];
    const float* W1   = (const float*)d_in[9];
    const float* b1   = (const float*)d_in[10];
    const float* W2   = (const float*)d_in[11];
    const float* b2   = (const float*)d_in[12];

    prep_kernel<<<64, 256>>>(Wih0, Whh0, bih0, bhh0, Wih1, Whh1, bih1, bhh1);

    size_t smem_bytes = (size_t)SMEMF * sizeof(float);   // 221184 B
    cudaFuncSetAttribute(lstm_fused,
                         cudaFuncAttributeMaxDynamicSharedMemorySize, (int)smem_bytes);
    lstm_fused<<<NCTA, NTHR, smem_bytes>>>(x, W1, b1, W2, b2, (float*)d_out);
}

// round 5
// speedup vs baseline: 1.2872x; 1.2871x over previous
#include <cuda_runtime.h>

#define BATCH 4096
#define SEQT  256
#define DIN   32
#define HID   64
#define GATES 256
#define BT    32
#define NTHR  256
#define NCTA  128
#define ST    36    // padded row stride (floats) for transposed activation buffers

typedef unsigned long long u64;

// ---- global scratch (transposed weights, fused biases) — R1-proven layout ----
__device__ __align__(16) float g_W0t[HID * GATES];     // Whh0^T [64][256]
__device__ __align__(16) float g_Wx0t[DIN * GATES];    // Wih0^T [32][256] (per-step LDG)
__device__ __align__(16) float g_W1t[2 * HID * GATES]; // [Wih1; Whh1]^T [128][256]
__device__ __align__(16) float g_b0[GATES];
__device__ __align__(16) float g_b1[GATES];

__global__ void prep_kernel(const float* __restrict__ Wih0, const float* __restrict__ Whh0,
                            const float* __restrict__ bih0, const float* __restrict__ bhh0,
                            const float* __restrict__ Wih1, const float* __restrict__ Whh1,
                            const float* __restrict__ bih1, const float* __restrict__ bhh1)
{
    int idx = blockIdx.x * blockDim.x + threadIdx.x;
    int total = HID * GATES + DIN * GATES + 2 * HID * GATES + 2 * GATES;
    for (int i = idx; i < total; i += gridDim.x * blockDim.x) {
        if (i < HID * GATES) {
            int k = i / GATES, n = i % GATES;
            g_W0t[i] = Whh0[n * HID + k];
        } else if (i < HID * GATES + DIN * GATES) {
            int j = i - HID * GATES;
            int k = j / GATES, n = j % GATES;
            g_Wx0t[j] = Wih0[n * DIN + k];
        } else if (i < HID * GATES + DIN * GATES + 2 * HID * GATES) {
            int j = i - HID * GATES - DIN * GATES;
            int k = j / GATES, n = j % GATES;
            g_W1t[j] = (k < HID) ? Wih1[n * HID + k] : Whh1[n * HID + (k - HID)];
        } else {
            int j = i - (HID * GATES + DIN * GATES + 2 * HID * GATES);
            if (j < GATES) g_b0[j] = bih0[j] + bhh0[j];
            else           g_b1[j - GATES] = bih1[j - GATES] + bhh1[j - GATES];
        }
    }
}

// ---- packed f32x2 helpers ----
__device__ __forceinline__ u64 fma2(u64 a, u64 b, u64 c) {
    u64 d;
    asm("fma.rn.f32x2 %0, %1, %2, %3;" : "=l"(d) : "l"(a), "l"(b), "l"(c));
    return d;
}
__device__ __forceinline__ u64 dup2(float x) {
    u64 d;
    asm("mov.b64 %0, {%1, %1};" : "=l"(d) : "f"(x));
    return d;
}
__device__ __forceinline__ float2 unpack2(u64 v) {
    float2 f;
    asm("mov.b64 {%0, %1}, %2;" : "=f"(f.x), "=f"(f.y) : "l"(v));
    return f;
}

// ---- fast activations (MUFU EX2/RCP, proven 2.6e-7 end-to-end) ----
__device__ __forceinline__ float fast_ex2(float x) {
    float y; asm("ex2.approx.f32 %0, %1;" : "=f"(y) : "f"(x)); return y;
}
__device__ __forceinline__ float fast_rcp(float x) {
    float y; asm("rcp.approx.f32 %0, %1;" : "=f"(y) : "f"(x)); return y;
}
__device__ __forceinline__ float sigf(float x) {
    return fast_rcp(1.0f + fast_ex2(-1.4426950408889634f * x));
}
__device__ __forceinline__ float tanhf_fast(float x) {
    x = fminf(fmaxf(x, -15.0f), 15.0f);
    float e = fast_ex2(-2.8853900817779268f * x);  // exp(-2x)
    return (1.0f - e) * fast_rcp(1.0f + e);
}

// R1-proven GEMM fragment: acc[m][g] += inT[k][m0..m0+3] * Wt[k][g*64+u0..+1]
template <bool GLOBAL_W, int K>
__device__ __forceinline__ void gemm_part(const float* __restrict__ inT,
                                          const float* __restrict__ Wt,
                                          int m0, int u0, u64 acc[4][4])
{
#pragma unroll 8
    for (int k = 0; k < K; k++) {
        float4 hv = *(const float4*)(inT + k * ST + m0);
        u64 w[4];
#pragma unroll
        for (int g = 0; g < 4; g++) {
            const float* wp = Wt + k * GATES + g * HID + u0;
            if (GLOBAL_W) w[g] = __ldg((const u64*)wp);
            else          w[g] = *(const u64*)wp;
        }
        u64 a;
        a = dup2(hv.x);
#pragma unroll
        for (int g = 0; g < 4; g++) acc[0][g] = fma2(a, w[g], acc[0][g]);
        a = dup2(hv.y);
#pragma unroll
        for (int g = 0; g < 4; g++) acc[1][g] = fma2(a, w[g], acc[1][g]);
        a = dup2(hv.z);
#pragma unroll
        for (int g = 0; g < 4; g++) acc[2][g] = fma2(a, w[g], acc[2][g]);
        a = dup2(hv.w);
#pragma unroll
        for (int g = 0; g < 4; g++) acc[3][g] = fma2(a, w[g], acc[3][g]);
    }
}

__device__ __forceinline__ void acc_init(const float* __restrict__ sB, int u0, u64 acc[4][4])
{
#pragma unroll
    for (int g = 0; g < 4; g++) {
        u64 bp = *(const u64*)(&sB[g * HID + u0]);
        acc[0][g] = bp; acc[1][g] = bp; acc[2][g] = bp; acc[3][g] = bp;
    }
}

// activations + cell update + write h (transposed): 4 rows x 2 cells per thread
__device__ __forceinline__ void lstm_update(u64 acc[4][4], float* __restrict__ cr,
                                            float* __restrict__ hT, int m0, int u0)
{
    float hn0[4], hn1[4];
#pragma unroll
    for (int m = 0; m < 4; m++) {
        float2 pi = unpack2(acc[m][0]);
        float2 pf = unpack2(acc[m][1]);
        float2 pg = unpack2(acc[m][2]);
        float2 po = unpack2(acc[m][3]);
        {
            float iv = sigf(pi.x), fv = sigf(pf.x), gv = tanhf_fast(pg.x), ov = sigf(po.x);
            float c = fv * cr[m * 2 + 0] + iv * gv;
            cr[m * 2 + 0] = c;
            hn0[m] = ov * tanhf_fast(c);
        }
        {
            float iv = sigf(pi.y), fv = sigf(pf.y), gv = tanhf_fast(pg.y), ov = sigf(po.y);
            float c = fv * cr[m * 2 + 1] + iv * gv;
            cr[m * 2 + 1] = c;
            hn1[m] = ov * tanhf_fast(c);
        }
    }
    *(float4*)(hT + (u0 + 0) * ST + m0) = make_float4(hn0[0], hn0[1], hn0[2], hn0[3]);
    *(float4*)(hT + (u0 + 1) * ST + m0) = make_float4(hn1[0], hn1[1], hn1[2], hn1[3]);
}

// Shared layout (floats) — identical footprint to R1 (221696 B)
#define OFF_W0   0
#define OFF_W1   (OFF_W0 + HID * GATES)
#define OFF_B0   (OFF_W1 + 2 * HID * GATES)
#define OFF_B1   (OFF_B0 + GATES)
#define OFF_H0T  (OFF_B1 + GATES)
#define OFF_H1T  (OFF_H0T + HID * ST)
#define OFF_XT   (OFF_H1T + HID * ST)
#define SMEM_FLOATS (OFF_XT + DIN * ST)

__global__ void __launch_bounds__(NTHR, 1)
lstm_fused(const float* __restrict__ x,
           const float* __restrict__ W1h, const float* __restrict__ b1h,
           const float* __restrict__ W2h, const float* __restrict__ b2h,
           float* __restrict__ out)
{
    extern __shared__ float sm[];
    float* sW0 = sm + OFF_W0;              // Whh0^T
    float* sW1 = sm + OFF_W1;              // [Wih1;Whh1]^T
    float* sB0 = sm + OFF_B0;
    float* sB1 = sm + OFF_B1;
    float* h0T = sm + OFF_H0T;
    float* h1T = sm + OFF_H1T;
    float* xT  = sm + OFF_XT;

    const int tid = threadIdx.x;
    const int b0  = blockIdx.x * BT;

    // stage weights + zero states
    for (int i = tid; i < HID * GATES / 4; i += NTHR)
        ((float4*)sW0)[i] = ((const float4*)g_W0t)[i];
    for (int i = tid; i < 2 * HID * GATES / 4; i += NTHR)
        ((float4*)sW1)[i] = ((const float4*)g_W1t)[i];
    if (tid < GATES) { sB0[tid] = g_b0[tid]; sB1[tid] = g_b1[tid]; }
    for (int i = tid; i < 2 * HID * ST; i += NTHR) h0T[i] = 0.0f;  // h0T+h1T contiguous

    const int gm = tid & 7;
    const int gn = tid >> 3;
    const int m0 = gm * 4;
    const int u0 = gn * 2;

    float c0r[8], c1r[8];
#pragma unroll
    for (int i = 0; i < 8; i++) { c0r[i] = 0.0f; c1r[i] = 0.0f; }

    // x staging: thread -> (row xm, float4 chunk xd)
    const int xm = tid >> 3;
    const int xd = tid & 7;
    const float* xptr = x + (size_t)(b0 + xm) * SEQT * DIN + xd * 4;

    // prologue: stage x(0), compute acc0(0) = b0 + Wih0*x(0)  (h0(-1)=0)
    float4 xv = *(const float4*)(xptr);
    xT[(4 * xd + 0) * ST + xm] = xv.x;
    xT[(4 * xd + 1) * ST + xm] = xv.y;
    xT[(4 * xd + 2) * ST + xm] = xv.z;
    xT[(4 * xd + 3) * ST + xm] = xv.w;
    __syncthreads();

    u64 acc0[4][4], acc1[4][4];
    acc_init(sB0, u0, acc0);
    gemm_part<true, DIN>(xT, g_Wx0t, m0, u0, acc0);
    xv = *(const float4*)(xptr + DIN);      // x(1)
    __syncthreads();                        // xT readers done before loop overwrites

    for (int t = 0; t < SEQT; t++) {
        // ---- P1: update0(t) (MUFU)  ||  Whh1*h1(t-1) (FFMA)  + stage x(t+1)
        lstm_update(acc0, c0r, h0T, m0, u0);            // writes h0(t)
        acc_init(sB1, u0, acc1);
        gemm_part<false, HID>(h1T, sW1 + HID * GATES, m0, u0, acc1);  // Whh1*h1(t-1)
        xT[(4 * xd + 0) * ST + xm] = xv.x;              // stage x(t+1)
        xT[(4 * xd + 1) * ST + xm] = xv.y;
        xT[(4 * xd + 2) * ST + xm] = xv.z;
        xT[(4 * xd + 3) * ST + xm] = xv.w;
        {
            int tn = (t + 2 < SEQT) ? t + 2 : SEQT - 1;
            xv = *(const float4*)(xptr + (size_t)tn * DIN);  // prefetch x(t+2)
        }
        __syncthreads();                                // B1: h0(t), x(t+1) visible

        // ---- P2: Wih1*h0(t) + Whh0(first half)*h0(t) + Wih0*x(t+1)  (pure FFMA)
        gemm_part<false, HID>(h0T, sW1, m0, u0, acc1);  // Wih1*h0(t)
        acc_init(sB0, u0, acc0);
        gemm_part<false, 32>(h0T, sW0, m0, u0, acc0);   // Whh0[k:0..31]
        gemm_part<true, DIN>(xT, g_Wx0t, m0, u0, acc0); // Wih0*x(t+1)

        // ---- P3 (no barrier): update1(t) (MUFU) || Whh0 second half (FFMA)
        gemm_part<false, 32>(h0T + 32 * ST, sW0 + 32 * GATES, m0, u0, acc0); // Whh0[k:32..63]
        lstm_update(acc1, c1r, h1T, m0, u0);            // writes h1(t)
        __syncthreads();                                // B2: h1(t) visible
    }

    // ---- head: out[m] = b2 + sum_n W2[n]*relu(b1[n] + sum_k h1(k,m) W1[n,k]) ----
    {
        int m = tid >> 3;      // 0..31
        int q = tid & 7;       // 0..7
        float pm = 0.0f;
#pragma unroll
        for (int jj = 0; jj < 8; jj++) {
            int n = q * 8 + jj;
            float s = b1h[n];
#pragma unroll 8
            for (int k = 0; k < HID; k++)
                s += h1T[k * ST + m] * W1h[n * HID + k];
            pm += fmaxf(s, 0.0f) * W2h[n];
        }
#pragma unroll
        for (int off = 4; off > 0; off >>= 1)
            pm += __shfl_down_sync(0xffffffffu, pm, off, 8);
        if (q == 0) out[b0 + m] = pm + b2h[0];
    }
}

extern "C" void kernel_launch(void* const* d_in, const int* in_sizes, int n_in,
                              void* d_out, int out_size)
{
    const float* x    = (const float*)d_in[0];
    const float* Wih0 = (const float*)d_in[1];
    const float* Whh0 = (const float*)d_in[2];
    const float* bih0 = (const float*)d_in[3];
    const float* bhh0 = (const float*)d_in[4];
    const float* Wih1 = (const float*)d_in[5];
    const float* Whh1 = (const float*)d_in[6];
    const float* bih1 = (const float*)d_in[7];
    const float* bhh1 = (const float*)d_in[8];
    const float* W1   = (const float*)d_in[9];
    const float* b1   = (const float*)d_in[10];
    const float* W2   = (const float*)d_in[11];
    const float* b2   = (const float*)d_in[12];

    prep_kernel<<<64, 256>>>(Wih0, Whh0, bih0, bhh0, Wih1, Whh1, bih1, bhh1);

    size_t smem_bytes = (size_t)SMEM_FLOATS * sizeof(float);  // 221696 B
    cudaFuncSetAttribute(lstm_fused,
                         cudaFuncAttributeMaxDynamicSharedMemorySize, (int)smem_bytes);
    lstm_fused<<<NCTA, NTHR, smem_bytes>>>(x, W1, b1, W2, b2, (float*)d_out);
}

// round 6
// speedup vs baseline: 1.2887x; 1.0012x over previous
#include <cuda_runtime.h>

#define BATCH 4096
#define SEQT  256
#define DIN   32
#define HID   64
#define GATES 256
#define BT    32
#define NTHR  256
#define NCTA  128
#define ST    36    // padded row stride (floats) for transposed activation buffers

typedef unsigned long long u64;

// ---- global scratch (transposed weights, fused biases) — R1-proven layout ----
__device__ __align__(16) float g_W0t[HID * GATES];     // Whh0^T [64][256]
__device__ __align__(16) float g_Wx0t[DIN * GATES];    // Wih0^T [32][256] (per-step LDG)
__device__ __align__(16) float g_W1t[2 * HID * GATES]; // [Wih1; Whh1]^T [128][256]
__device__ __align__(16) float g_b0[GATES];
__device__ __align__(16) float g_b1[GATES];

__global__ void prep_kernel(const float* __restrict__ Wih0, const float* __restrict__ Whh0,
                            const float* __restrict__ bih0, const float* __restrict__ bhh0,
                            const float* __restrict__ Wih1, const float* __restrict__ Whh1,
                            const float* __restrict__ bih1, const float* __restrict__ bhh1)
{
    int idx = blockIdx.x * blockDim.x + threadIdx.x;
    int total = HID * GATES + DIN * GATES + 2 * HID * GATES + 2 * GATES;
    for (int i = idx; i < total; i += gridDim.x * blockDim.x) {
        if (i < HID * GATES) {
            int k = i / GATES, n = i % GATES;
            g_W0t[i] = Whh0[n * HID + k];
        } else if (i < HID * GATES + DIN * GATES) {
            int j = i - HID * GATES;
            int k = j / GATES, n = j % GATES;
            g_Wx0t[j] = Wih0[n * DIN + k];
        } else if (i < HID * GATES + DIN * GATES + 2 * HID * GATES) {
            int j = i - HID * GATES - DIN * GATES;
            int k = j / GATES, n = j % GATES;
            g_W1t[j] = (k < HID) ? Wih1[n * HID + k] : Whh1[n * HID + (k - HID)];
        } else {
            int j = i - (HID * GATES + DIN * GATES + 2 * HID * GATES);
            if (j < GATES) g_b0[j] = bih0[j] + bhh0[j];
            else           g_b1[j - GATES] = bih1[j - GATES] + bhh1[j - GATES];
        }
    }
}

// ---- packed f32x2 helpers ----
__device__ __forceinline__ u64 fma2(u64 a, u64 b, u64 c) {
    u64 d;
    asm("fma.rn.f32x2 %0, %1, %2, %3;" : "=l"(d) : "l"(a), "l"(b), "l"(c));
    return d;
}
__device__ __forceinline__ u64 dup2(float x) {
    u64 d;
    asm("mov.b64 %0, {%1, %1};" : "=l"(d) : "f"(x));
    return d;
}
__device__ __forceinline__ float2 unpack2(u64 v) {
    float2 f;
    asm("mov.b64 {%0, %1}, %2;" : "=f"(f.x), "=f"(f.y) : "l"(v));
    return f;
}

// ---- fast activations (MUFU EX2/RCP, proven 2.6e-7 end-to-end) ----
__device__ __forceinline__ float fast_ex2(float x) {
    float y; asm("ex2.approx.f32 %0, %1;" : "=f"(y) : "f"(x)); return y;
}
__device__ __forceinline__ float fast_rcp(float x) {
    float y; asm("rcp.approx.f32 %0, %1;" : "=f"(y) : "f"(x)); return y;
}
__device__ __forceinline__ float sigf(float x) {
    return fast_rcp(1.0f + fast_ex2(-1.4426950408889634f * x));
}
__device__ __forceinline__ float tanhf_fast(float x) {
    x = fminf(fmaxf(x, -15.0f), 15.0f);
    float e = fast_ex2(-2.8853900817779268f * x);  // exp(-2x)
    return (1.0f - e) * fast_rcp(1.0f + e);
}

// R1-proven GEMM fragment: acc[m][g] += inT[k][m0..m0+3] * Wt[k][g*64+u0..+1]
template <bool GLOBAL_W, int K>
__device__ __forceinline__ void gemm_part(const float* __restrict__ inT,
                                          const float* __restrict__ Wt,
                                          int m0, int u0, u64 acc[4][4])
{
#pragma unroll 8
    for (int k = 0; k < K; k++) {
        float4 hv = *(const float4*)(inT + k * ST + m0);
        u64 w[4];
#pragma unroll
        for (int g = 0; g < 4; g++) {
            const float* wp = Wt + k * GATES + g * HID + u0;
            if (GLOBAL_W) w[g] = __ldg((const u64*)wp);
            else          w[g] = *(const u64*)wp;
        }
        u64 a;
        a = dup2(hv.x);
#pragma unroll
        for (int g = 0; g < 4; g++) acc[0][g] = fma2(a, w[g], acc[0][g]);
        a = dup2(hv.y);
#pragma unroll
        for (int g = 0; g < 4; g++) acc[1][g] = fma2(a, w[g], acc[1][g]);
        a = dup2(hv.z);
#pragma unroll
        for (int g = 0; g < 4; g++) acc[2][g] = fma2(a, w[g], acc[2][g]);
        a = dup2(hv.w);
#pragma unroll
        for (int g = 0; g < 4; g++) acc[3][g] = fma2(a, w[g], acc[3][g]);
    }
}

__device__ __forceinline__ void acc_init(const float* __restrict__ sB, int u0, u64 acc[4][4])
{
#pragma unroll
    for (int g = 0; g < 4; g++) {
        u64 bp = *(const u64*)(&sB[g * HID + u0]);
        acc[0][g] = bp; acc[1][g] = bp; acc[2][g] = bp; acc[3][g] = bp;
    }
}

// activations + cell update + write h (transposed): 4 rows x 2 cells per thread
__device__ __forceinline__ void lstm_update(u64 acc[4][4], float* __restrict__ cr,
                                            float* __restrict__ hT, int m0, int u0)
{
    float hn0[4], hn1[4];
#pragma unroll
    for (int m = 0; m < 4; m++) {
        float2 pi = unpack2(acc[m][0]);
        float2 pf = unpack2(acc[m][1]);
        float2 pg = unpack2(acc[m][2]);
        float2 po = unpack2(acc[m][3]);
        {
            float iv = sigf(pi.x), fv = sigf(pf.x), gv = tanhf_fast(pg.x), ov = sigf(po.x);
            float c = fv * cr[m * 2 + 0] + iv * gv;
            cr[m * 2 + 0] = c;
            hn0[m] = ov * tanhf_fast(c);
        }
        {
            float iv = sigf(pi.y), fv = sigf(pf.y), gv = tanhf_fast(pg.y), ov = sigf(po.y);
            float c = fv * cr[m * 2 + 1] + iv * gv;
            cr[m * 2 + 1] = c;
            hn1[m] = ov * tanhf_fast(c);
        }
    }
    *(float4*)(hT + (u0 + 0) * ST + m0) = make_float4(hn0[0], hn0[1], hn0[2], hn0[3]);
    *(float4*)(hT + (u0 + 1) * ST + m0) = make_float4(hn1[0], hn1[1], hn1[2], hn1[3]);
}

// Shared layout (floats) — identical footprint to R1 (221696 B)
#define OFF_W0   0
#define OFF_W1   (OFF_W0 + HID * GATES)
#define OFF_B0   (OFF_W1 + 2 * HID * GATES)
#define OFF_B1   (OFF_B0 + GATES)
#define OFF_H0T  (OFF_B1 + GATES)
#define OFF_H1T  (OFF_H0T + HID * ST)
#define OFF_XT   (OFF_H1T + HID * ST)
#define SMEM_FLOATS (OFF_XT + DIN * ST)

__global__ void __launch_bounds__(NTHR, 1)
lstm_fused(const float* __restrict__ x,
           const float* __restrict__ W1h, const float* __restrict__ b1h,
           const float* __restrict__ W2h, const float* __restrict__ b2h,
           float* __restrict__ out)
{
    extern __shared__ float sm[];
    float* sW0 = sm + OFF_W0;              // Whh0^T
    float* sW1 = sm + OFF_W1;              // [Wih1;Whh1]^T
    float* sB0 = sm + OFF_B0;
    float* sB1 = sm + OFF_B1;
    float* h0T = sm + OFF_H0T;
    float* h1T = sm + OFF_H1T;
    float* xT  = sm + OFF_XT;

    const int tid = threadIdx.x;
    const int b0  = blockIdx.x * BT;

    // stage weights + zero states
    for (int i = tid; i < HID * GATES / 4; i += NTHR)
        ((float4*)sW0)[i] = ((const float4*)g_W0t)[i];
    for (int i = tid; i < 2 * HID * GATES / 4; i += NTHR)
        ((float4*)sW1)[i] = ((const float4*)g_W1t)[i];
    if (tid < GATES) { sB0[tid] = g_b0[tid]; sB1[tid] = g_b1[tid]; }
    for (int i = tid; i < 2 * HID * ST; i += NTHR) h0T[i] = 0.0f;  // h0T+h1T contiguous

    const int gm = tid & 7;
    const int gn = tid >> 3;
    const int m0 = gm * 4;
    const int u0 = gn * 2;

    float c0r[8], c1r[8];
#pragma unroll
    for (int i = 0; i < 8; i++) { c0r[i] = 0.0f; c1r[i] = 0.0f; }

    // x staging: thread -> (row xm, float4 chunk xd)
    const int xm = tid >> 3;
    const int xd = tid & 7;
    const float* xptr = x + (size_t)(b0 + xm) * SEQT * DIN + xd * 4;

    // prologue: stage x(0), compute acc0(0) = b0 + Wih0*x(0)  (h0(-1)=0)
    float4 xv = *(const float4*)(xptr);
    xT[(4 * xd + 0) * ST + xm] = xv.x;
    xT[(4 * xd + 1) * ST + xm] = xv.y;
    xT[(4 * xd + 2) * ST + xm] = xv.z;
    xT[(4 * xd + 3) * ST + xm] = xv.w;
    __syncthreads();

    u64 acc0[4][4], acc1[4][4];
    acc_init(sB0, u0, acc0);
    gemm_part<true, DIN>(xT, g_Wx0t, m0, u0, acc0);
    xv = *(const float4*)(xptr + DIN);      // x(1)
    __syncthreads();                        // xT readers done before loop overwrites

    for (int t = 0; t < SEQT; t++) {
        // ---- P1: update0(t) (MUFU)  ||  Whh1*h1(t-1) (FFMA)  + stage x(t+1)
        lstm_update(acc0, c0r, h0T, m0, u0);            // writes h0(t)
        acc_init(sB1, u0, acc1);
        gemm_part<false, HID>(h1T, sW1 + HID * GATES, m0, u0, acc1);  // Whh1*h1(t-1)
        xT[(4 * xd + 0) * ST + xm] = xv.x;              // stage x(t+1)
        xT[(4 * xd + 1) * ST + xm] = xv.y;
        xT[(4 * xd + 2) * ST + xm] = xv.z;
        xT[(4 * xd + 3) * ST + xm] = xv.w;
        {
            int tn = (t + 2 < SEQT) ? t + 2 : SEQT - 1;
            xv = *(const float4*)(xptr + (size_t)tn * DIN);  // prefetch x(t+2)
        }
        __syncthreads();                                // B1: h0(t), x(t+1) visible

        // ---- P2: Wih1*h0(t) + Whh0(first half)*h0(t) + Wih0*x(t+1)  (pure FFMA)
        gemm_part<false, HID>(h0T, sW1, m0, u0, acc1);  // Wih1*h0(t)
        acc_init(sB0, u0, acc0);
        gemm_part<false, 32>(h0T, sW0, m0, u0, acc0);   // Whh0[k:0..31]
        gemm_part<true, DIN>(xT, g_Wx0t, m0, u0, acc0); // Wih0*x(t+1)

        // ---- P3 (no barrier): update1(t) (MUFU) || Whh0 second half (FFMA)
        gemm_part<false, 32>(h0T + 32 * ST, sW0 + 32 * GATES, m0, u0, acc0); // Whh0[k:32..63]
        lstm_update(acc1, c1r, h1T, m0, u0);            // writes h1(t)
        __syncthreads();                                // B2: h1(t) visible
    }

    // ---- head: out[m] = b2 + sum_n W2[n]*relu(b1[n] + sum_k h1(k,m) W1[n,k]) ----
    {
        int m = tid >> 3;      // 0..31
        int q = tid & 7;       // 0..7
        float pm = 0.0f;
#pragma unroll
        for (int jj = 0; jj < 8; jj++) {
            int n = q * 8 + jj;
            float s = b1h[n];
#pragma unroll 8
            for (int k = 0; k < HID; k++)
                s += h1T[k * ST + m] * W1h[n * HID + k];
            pm += fmaxf(s, 0.0f) * W2h[n];
        }
#pragma unroll
        for (int off = 4; off > 0; off >>= 1)
            pm += __shfl_down_sync(0xffffffffu, pm, off, 8);
        if (q == 0) out[b0 + m] = pm + b2h[0];
    }
}

extern "C" void kernel_launch(void* const* d_in, const int* in_sizes, int n_in,
                              void* d_out, int out_size)
{
    const float* x    = (const float*)d_in[0];
    const float* Wih0 = (const float*)d_in[1];
    const float* Whh0 = (const float*)d_in[2];
    const float* bih0 = (const float*)d_in[3];
    const float* bhh0 = (const float*)d_in[4];
    const float* Wih1 = (const float*)d_in[5];
    const float* Whh1 = (const float*)d_in[6];
    const float* bih1 = (const float*)d_in[7];
    const float* bhh1 = (const float*)d_in[8];
    const float* W1   = (const float*)d_in[9];
    const float* b1   = (const float*)d_in[10];
    const float* W2   = (const float*)d_in[11];
    const float* b2   = (const float*)d_in[12];

    prep_kernel<<<64, 256>>>(Wih0, Whh0, bih0, bhh0, Wih1, Whh1, bih1, bhh1);

    size_t smem_bytes = (size_t)SMEM_FLOATS * sizeof(float);  // 221696 B
    cudaFuncSetAttribute(lstm_fused,
                         cudaFuncAttributeMaxDynamicSharedMemorySize, (int)smem_bytes);
    lstm_fused<<<NCTA, NTHR, smem_bytes>>>(x, W1, b1, W2, b2, (float*)d_out);
}